// round 4
// baseline (speedup 1.0000x reference)
#include <cuda_runtime.h>
#include <math.h>
#include <float.h>

// Problem constants (fixed shapes for this benchmark)
#define cN 20000
#define cE 320000
#define cL 128
#define cMAXIT 10

// ---------------- device scratch (no allocations allowed) ----------------
__device__ __align__(16) float g_z2 [(size_t)2*cN*cL];     // z variants (reach=0, reach=1)
__device__ __align__(16) float g_ZP [(size_t)2*cN*2*cL];   // [z0;z1] @ [W1a|W2a]
__device__ __align__(16) float g_HP [(size_t)cN*2*cL];     // h @ [W1b|W2b]
__device__ __align__(16) float g_P1 [(size_t)cN*cL];
__device__ __align__(16) float g_P2 [(size_t)cN*cL];       // includes +b_msg
__device__ __align__(16) float g_h  [(size_t)cN*cL];
__device__ __align__(16) float g_agg[(size_t)cN*cL];
__device__ __align__(16) float g_Ba [128*256];             // [W1a | W2a]
__device__ __align__(16) float g_Bh [128*256];             // [W1b | W2b]
__device__ float g_a1[cN], g_a2[cN], g_reach[cN];
__device__ unsigned g_mx[cN], g_mxd[cN];
__device__ int g_cnt[cN], g_ptr[cN+1], g_fill[cN], g_csrc[cE], g_best[cN];

// ---------------- small utility kernels ----------------
__global__ void k_init(int n, int e) {
    int i = blockIdx.x * blockDim.x + threadIdx.x;
    if (i < n) { g_cnt[i] = 0; g_mx[i] = 0u; g_mxd[i] = 0u; g_best[i] = e; }
}

// pack B matrices:  Ba[k][j] = (j<128 ? W1[k][j] : W2[k][j-128])        (k = z rows 0..127)
//                   Bh[k][j] = (j<128 ? W1[128+k][j] : W2[128+k][j-128]) (h rows)
__global__ void k_pack(const float* __restrict__ W1, const float* __restrict__ W2) {
    int idx = blockIdx.x * blockDim.x + threadIdx.x;
    if (idx < 128 * 256) {
        int k = idx >> 8, j = idx & 255;
        float a = (j < 128) ? W1[k*128 + j]       : W2[k*128 + (j-128)];
        float b = (j < 128) ? W1[(128+k)*128 + j] : W2[(128+k)*128 + (j-128)];
        g_Ba[idx] = a; g_Bh[idx] = b;
    }
}

// z for both reach variants: z_v = relu(pos*We0 + v*We1 + be)
__global__ void k_z(const float* __restrict__ pos, const float* __restrict__ We,
                    const float* __restrict__ be, int n) {
    int idx = blockIdx.x * blockDim.x + threadIdx.x;
    if (idx < n * 128) {
        int i = idx >> 7, j = idx & 127;
        float t = pos[i] * We[j] + be[j];
        g_z2[idx]                       = fmaxf(t, 0.f);
        g_z2[(size_t)n*128 + idx]       = fmaxf(t + We[128 + j], 0.f);
    }
}

// ---------------- SGEMM: C[M,Nc] = A[M,K] @ B[K,Nc] (+bias, relu) ----------------
// BM=64, BN=64, BK=16, 256 threads, 4x4 per thread.
#define BM 64
#define BN 64
#define BK 16
__global__ void __launch_bounds__(256) k_sgemm(
    const float* __restrict__ A, const float* __restrict__ B, float* __restrict__ C,
    int M, int Nc, int K, const float* __restrict__ bias, int doRelu)
{
    __shared__ float As[BK][BM + 4];
    __shared__ float Bs[BK][BN + 4];
    int tid = threadIdx.x;
    int m0 = blockIdx.x * BM, n0 = blockIdx.y * BN;
    int tx = tid & 15, ty = tid >> 4;
    int am = tid >> 2, aq = tid & 3;          // A loader: row am, quarter aq
    int bw = tid & 15, bk = tid >> 4;         // B loader: float4 col bw, row bk
    float acc[4][4];
    #pragma unroll
    for (int i = 0; i < 4; i++)
        #pragma unroll
        for (int j = 0; j < 4; j++) acc[i][j] = 0.f;

    for (int k0 = 0; k0 < K; k0 += BK) {
        float4 av;
        int arow = m0 + am;
        if (arow < M) av = *(const float4*)(A + (size_t)arow * K + k0 + aq * 4);
        else          av = make_float4(0.f, 0.f, 0.f, 0.f);
        As[aq*4+0][am] = av.x; As[aq*4+1][am] = av.y;
        As[aq*4+2][am] = av.z; As[aq*4+3][am] = av.w;
        float4 bv = *(const float4*)(B + (size_t)(k0 + bk) * Nc + n0 + bw * 4);
        *(float4*)&Bs[bk][bw * 4] = bv;
        __syncthreads();
        #pragma unroll
        for (int kk = 0; kk < BK; kk++) {
            float4 a4 = *(const float4*)&As[kk][ty * 4];
            float4 b4 = *(const float4*)&Bs[kk][tx * 4];
            acc[0][0] += a4.x * b4.x; acc[0][1] += a4.x * b4.y; acc[0][2] += a4.x * b4.z; acc[0][3] += a4.x * b4.w;
            acc[1][0] += a4.y * b4.x; acc[1][1] += a4.y * b4.y; acc[1][2] += a4.y * b4.z; acc[1][3] += a4.y * b4.w;
            acc[2][0] += a4.z * b4.x; acc[2][1] += a4.z * b4.y; acc[2][2] += a4.z * b4.z; acc[2][3] += a4.z * b4.w;
            acc[3][0] += a4.w * b4.x; acc[3][1] += a4.w * b4.y; acc[3][2] += a4.w * b4.z; acc[3][3] += a4.w * b4.w;
        }
        __syncthreads();
    }
    #pragma unroll
    for (int i = 0; i < 4; i++) {
        int row = m0 + ty * 4 + i;
        if (row < M) {
            #pragma unroll
            for (int j = 0; j < 4; j++) {
                int col = n0 + tx * 4 + j;
                float v = acc[i][j];
                if (bias) v += bias[col];
                if (doRelu) v = fmaxf(v, 0.f);
                C[(size_t)row * Nc + col] = v;
            }
        }
    }
}

// ---------------- CSR build over dst ----------------
__global__ void k_count(const int* __restrict__ dst, int e) {
    int idx = blockIdx.x * blockDim.x + threadIdx.x;
    if (idx < e) atomicAdd(&g_cnt[dst[idx]], 1);
}
__global__ void k_scan(int n) {
    __shared__ int sm[1024];
    __shared__ int carry;
    int t = threadIdx.x;
    if (t == 0) carry = 0;
    __syncthreads();
    for (int base = 0; base < n; base += 1024) {
        int v = (base + t < n) ? g_cnt[base + t] : 0;
        int x = v;
        for (int off = 1; off < 1024; off <<= 1) {
            sm[t] = x; __syncthreads();
            if (t >= off) x += sm[t - off];
            __syncthreads();
        }
        int c = carry;
        if (base + t < n) { g_ptr[base + t] = c + x - v; g_fill[base + t] = c + x - v; }
        __syncthreads();
        if (t == 1023) carry = c + x;
        __syncthreads();
    }
    if (t == 0) g_ptr[n] = carry;
}
__global__ void k_fill(const int* __restrict__ src, const int* __restrict__ dst, int e) {
    int idx = blockIdx.x * blockDim.x + threadIdx.x;
    if (idx < e) {
        int p = atomicAdd(&g_fill[dst[idx]], 1);
        g_csrc[p] = src[idx];
    }
}

// ---------------- per-iteration kernels ----------------
// P1 = ZP[sel].first + HP.first ; P2 = ZP[sel].second + HP.second + b_msg
__global__ void k_combine(const float* __restrict__ s, const float* __restrict__ bmsg,
                          int n, int useHP, int useS) {
    int idx = blockIdx.x * blockDim.x + threadIdx.x;
    if (idx < n * 128) {
        int i = idx >> 7, j = idx & 127;
        float rv = useS ? s[i] : g_reach[i];
        size_t zoff = ((rv > 0.5f) ? (size_t)n * 256 : 0) + (size_t)i * 256;
        float hp1 = 0.f, hp2 = 0.f;
        if (useHP) {
            hp1 = g_HP[(size_t)i * 256 + j];
            hp2 = g_HP[(size_t)i * 256 + 128 + j];
        }
        g_P1[idx] = g_ZP[zoff + j] + hp1;
        g_P2[idx] = g_ZP[zoff + 128 + j] + hp2 + bmsg[j];
    }
}

// one warp per destination node; relu(max(P1[src]) + P2c[dst]) exact (monotone hoist)
__global__ void k_agg(int n) {
    int gw = (blockIdx.x * blockDim.x + threadIdx.x) >> 5;
    int lane = threadIdx.x & 31;
    if (gw >= n) return;
    float4 c = ((const float4*)g_P2)[(size_t)gw * 32 + lane];
    int beg = g_ptr[gw], end = g_ptr[gw + 1];
    float4 m = make_float4(-FLT_MAX, -FLT_MAX, -FLT_MAX, -FLT_MAX);
    for (int t = beg; t < end; t++) {
        int sidx = g_csrc[t];
        float4 p = ((const float4*)g_P1)[(size_t)sidx * 32 + lane];
        m.x = fmaxf(m.x, p.x); m.y = fmaxf(m.y, p.y);
        m.z = fmaxf(m.z, p.z); m.w = fmaxf(m.w, p.w);
    }
    float4 o;
    if (end > beg) {
        o.x = fmaxf(m.x + c.x, 0.f); o.y = fmaxf(m.y + c.y, 0.f);
        o.z = fmaxf(m.z + c.z, 0.f); o.w = fmaxf(m.w + c.w, 0.f);
    } else {
        o = make_float4(0.f, 0.f, 0.f, 0.f);
    }
    ((float4*)g_agg)[(size_t)gw * 32 + lane] = o;
}

// decoder per-node scalars a1 = h . Wdec[0:128], a2 = h . Wdec[128:256]
__global__ void k_a12(const float* __restrict__ Wdec, int n) {
    int gw = (blockIdx.x * blockDim.x + threadIdx.x) >> 5;
    int lane = threadIdx.x & 31;
    if (gw >= n) return;
    float4 h4 = ((const float4*)g_h)[(size_t)gw * 32 + lane];
    float4 w1 = ((const float4*)Wdec)[lane];
    float4 w2 = ((const float4*)Wdec)[32 + lane];
    float s1 = h4.x * w1.x + h4.y * w1.y + h4.z * w1.z + h4.w * w1.w;
    float s2 = h4.x * w2.x + h4.y * w2.y + h4.z * w2.z + h4.w * w2.w;
    #pragma unroll
    for (int o = 16; o > 0; o >>= 1) {
        s1 += __shfl_xor_sync(0xffffffffu, s1, o);
        s2 += __shfl_xor_sync(0xffffffffu, s2, o);
    }
    if (lane == 0) { g_a1[gw] = s1; g_a2[gw] = s2; }
}

__device__ __forceinline__ float sigmoidf_(float x) {
    if (x >= 0.f) return 1.f / (1.f + expf(-x));
    float e = expf(x);
    return e / (1.f + e);
}

__global__ void k_alpha(const int* __restrict__ src, const int* __restrict__ dst,
                        const float* __restrict__ bdec, float* __restrict__ preds,
                        int e, int isLast) {
    int idx = blockIdx.x * blockDim.x + threadIdx.x;
    if (idx < e) {
        int si = src[idx], di = dst[idx];
        float lg = g_a1[si] + g_a2[di] + bdec[0];
        float al = sigmoidf_(lg);
        preds[idx] = al;
        unsigned u = __float_as_uint(al);   // alpha > 0 -> bit order == float order
        atomicMax(&g_mx[si], u);
        atomicMax(&g_mx[di], u);
        if (isLast) atomicMax(&g_mxd[di], u);
    }
}

__global__ void k_reach(int n) {
    int i = blockIdx.x * blockDim.x + threadIdx.x;
    if (i < n) {
        g_reach[i] = (__uint_as_float(g_mx[i]) >= 0.4f) ? 1.f : 0.f;
        g_mx[i] = 0u;   // reset for next iteration
    }
}

__global__ void k_winner(const int* __restrict__ dst, const float* __restrict__ lastpred, int e) {
    int idx = blockIdx.x * blockDim.x + threadIdx.x;
    if (idx < e) {
        int d = dst[idx];
        if (__float_as_uint(lastpred[idx]) == g_mxd[d]) atomicMin(&g_best[d], idx);
    }
}

__global__ void k_final(const int* __restrict__ src, float* __restrict__ out_reach,
                        float* __restrict__ out_par, int n, int e) {
    int i = blockIdx.x * blockDim.x + threadIdx.x;
    if (i < n) {
        out_reach[i] = g_reach[i];
        int b = g_best[i];
        out_par[i] = (float)(b < e ? src[b] : i);
    }
}

// ---------------- host launcher (graph-capturable) ----------------
extern "C" void kernel_launch(void* const* d_in, const int* in_sizes, int n_in,
                              void* d_out, int out_size) {
    const float* pos  = (const float*)d_in[0];
    const float* s    = (const float*)d_in[1];
    const int*   ei   = (const int*)  d_in[2];
    const float* Wenc = (const float*)d_in[3];
    const float* benc = (const float*)d_in[4];
    const float* W1   = (const float*)d_in[5];
    const float* W2   = (const float*)d_in[6];
    const float* bmsg = (const float*)d_in[7];
    const float* Wout = (const float*)d_in[8];
    const float* bout = (const float*)d_in[9];
    const float* Wdec = (const float*)d_in[10];
    const float* bdec = (const float*)d_in[11];

    int N = in_sizes[0];
    int E = in_sizes[2] / 2;
    if (N > cN || E > cE || N <= 0 || E <= 0) return;
    int MAXIT = (out_size - 2 * N) / E;
    if (MAXIT < 1) MAXIT = 1;
    if (MAXIT > cMAXIT) MAXIT = cMAXIT;

    const int* srcA = ei;
    const int* dstA = ei + E;
    float* out = (float*)d_out;

    void *pz2, *pZP, *pHP, *ph, *pagg, *pBa, *pBh;
    cudaGetSymbolAddress(&pz2,  g_z2);
    cudaGetSymbolAddress(&pZP,  g_ZP);
    cudaGetSymbolAddress(&pHP,  g_HP);
    cudaGetSymbolAddress(&ph,   g_h);
    cudaGetSymbolAddress(&pagg, g_agg);
    cudaGetSymbolAddress(&pBa,  g_Ba);
    cudaGetSymbolAddress(&pBh,  g_Bh);

    // ---- setup ----
    k_init<<<(N + 255) / 256, 256>>>(N, E);
    k_pack<<<128, 256>>>(W1, W2);
    k_z<<<(N * 128 + 255) / 256, 256>>>(pos, Wenc, benc, N);
    {   // ZP = [z0;z1] @ Ba   (2N x 256, K=128) — once per launch
        dim3 g((2 * N + BM - 1) / BM, 256 / BN);
        k_sgemm<<<g, 256>>>((const float*)pz2, (const float*)pBa, (float*)pZP,
                            2 * N, 256, 128, nullptr, 0);
    }
    k_count<<<(E + 255) / 256, 256>>>(dstA, E);
    k_scan<<<1, 1024>>>(N);
    k_fill<<<(E + 255) / 256, 256>>>(srcA, dstA, E);

    // ---- iterations ----
    for (int it = 0; it < MAXIT; ++it) {
        if (it > 0) {   // HP = h @ Bh   (N x 256, K=128)
            dim3 g((N + BM - 1) / BM, 256 / BN);
            k_sgemm<<<g, 256>>>((const float*)ph, (const float*)pBh, (float*)pHP,
                                N, 256, 128, nullptr, 0);
        }
        k_combine<<<(N * 128 + 255) / 256, 256>>>(s, bmsg, N, it > 0 ? 1 : 0, it == 0 ? 1 : 0);
        k_agg<<<(N + 7) / 8, 256>>>(N);
        {   // h = relu(agg @ Wout + bout)   (N x 128, K=128)
            dim3 g((N + BM - 1) / BM, 128 / BN);
            k_sgemm<<<g, 256>>>((const float*)pagg, Wout, (float*)ph,
                                N, 128, 128, bout, 1);
        }
        k_a12<<<(N + 7) / 8, 256>>>(Wdec, N);
        k_alpha<<<(E + 255) / 256, 256>>>(srcA, dstA, bdec, out + (size_t)it * E,
                                          E, (it == MAXIT - 1) ? 1 : 0);
        k_reach<<<(N + 255) / 256, 256>>>(N);
    }

    // ---- parents + outputs ----
    k_winner<<<(E + 255) / 256, 256>>>(dstA, out + (size_t)(MAXIT - 1) * E, E);
    k_final<<<(N + 255) / 256, 256>>>(srcA, out + (size_t)MAXIT * E,
                                      out + (size_t)MAXIT * E + N, N, E);
}